// round 15
// baseline (speedup 1.0000x reference)
#include <cuda_runtime.h>
#include <cuda_fp16.h>
#include <cstdint>

#define TT 2048
#define NN 4096
#define NHT 8
#define AP2 72       // pitch for 64-wide K tiles (144B rows, conflict-free LDSM)
#define BPITCH 136   // pitch for 128-wide tiles (272B rows, conflict-free LDSM.T)
#define TRPITCH 136

// fp16 scratch (allocation-free device globals)
__device__ __align__(128) __half g_QRh[(size_t)NHT * TT * NN];
__device__ __align__(128) __half g_Vh[(size_t)NHT * TT * NN];
__device__ __align__(128) __half g_Sh[(size_t)NHT * TT * TT];

__device__ __forceinline__ uint32_t smaddr(const void* p) {
    return (uint32_t)__cvta_generic_to_shared(p);
}
__device__ __forceinline__ void ldsm4(uint32_t* r, uint32_t a) {
    asm volatile("ldmatrix.sync.aligned.m8n8.x4.shared.b16 {%0,%1,%2,%3},[%4];"
                 : "=r"(r[0]), "=r"(r[1]), "=r"(r[2]), "=r"(r[3]) : "r"(a));
}
__device__ __forceinline__ void ldsm4t(uint32_t* r, uint32_t a) {
    asm volatile("ldmatrix.sync.aligned.m8n8.x4.trans.shared.b16 {%0,%1,%2,%3},[%4];"
                 : "=r"(r[0]), "=r"(r[1]), "=r"(r[2]), "=r"(r[3]) : "r"(a));
}
__device__ __forceinline__ void mmaf16(float* d, const uint32_t* a, const uint32_t* b) {
    asm volatile("mma.sync.aligned.m16n8k16.row.col.f32.f16.f16.f32 "
                 "{%0,%1,%2,%3},{%4,%5,%6,%7},{%8,%9},{%0,%1,%2,%3};"
                 : "+f"(d[0]), "+f"(d[1]), "+f"(d[2]), "+f"(d[3])
                 : "r"(a[0]), "r"(a[1]), "r"(a[2]), "r"(a[3]), "r"(b[0]), "r"(b[1]));
}
__device__ __forceinline__ void cpa16(uint32_t dst, const void* src) {
    asm volatile("cp.async.cg.shared.global [%0],[%1],16;" :: "r"(dst), "l"(src));
}
__device__ __forceinline__ void cp_commit() { asm volatile("cp.async.commit_group;" ::: "memory"); }
template <int N> __device__ __forceinline__ void cp_wait() {
    asm volatile("cp.async.wait_group %0;" :: "n"(N) : "memory");
}

// ---------------------------------------------------------------------------
// Kernel 1 (merged prep): RoPE->fp16 (pre-scaled 1/8) + V->fp16
// ---------------------------------------------------------------------------
#define PREP_BLOCKS 32768   // NHT*TT*NN/8/256

__global__ void prep(const float* __restrict__ Q, const float* __restrict__ V) {
    if (blockIdx.x < PREP_BLOCKS) {
        size_t p0 = ((size_t)blockIdx.x * blockDim.x + threadIdx.x) * 4;
        int n2 = (int)(p0 % (NN / 2));
        size_t row = p0 / (NN / 2);
        int t = (int)(row % TT);
        const float inv2pi = 0.15915494309189535f;
        float4 vin0 = *(const float4*)((const float*)Q + p0 * 2);
        float4 vin1 = *(const float4*)((const float*)Q + p0 * 2 + 4);
        float vx[4] = {vin0.x, vin0.z, vin1.x, vin1.z};
        float vy[4] = {vin0.y, vin0.w, vin1.y, vin1.w};
        __half2 out[4];
#pragma unroll
        for (int j = 0; j < 4; j++) {
            float freq = exp2f(-(float)((n2 + j) * 2) * (1.0f / 256.0f)) * inv2pi;
            float ph = (float)t * freq;
            float fr = ph - floorf(ph);
            float s, c;
            sincospif(2.0f * fr, &s, &c);
            float ox = (vx[j] * c - vy[j] * s) * 0.125f;
            float oy = (vy[j] * c + vx[j] * s) * 0.125f;
            out[j] = __halves2half2(__float2half_rn(ox), __float2half_rn(oy));
        }
        *(uint4*)(g_QRh + p0 * 2) = *(uint4*)out;
    } else {
        size_t i = ((size_t)(blockIdx.x - PREP_BLOCKS) * blockDim.x + threadIdx.x) * 8;
        float4 v0 = *(const float4*)(V + i);
        float4 v1 = *(const float4*)(V + i + 4);
        __half2 o[4];
        o[0] = __halves2half2(__float2half_rn(v0.x), __float2half_rn(v0.y));
        o[1] = __halves2half2(__float2half_rn(v0.z), __float2half_rn(v0.w));
        o[2] = __halves2half2(__float2half_rn(v1.x), __float2half_rn(v1.y));
        o[3] = __halves2half2(__float2half_rn(v1.z), __float2half_rn(v1.w));
        *(uint4*)(g_Vh + i) = *(uint4*)o;
    }
}

// ---------------------------------------------------------------------------
// Kernel 2: S = QRs QRs^T  (single term; upper-tri blocks + mirror via smem
// transpose; K-chunk 64, 3 stages, 2 CTAs/SM; A-fragment double-buffered;
// next-stage load issued right after the barrier)
// ---------------------------------------------------------------------------
#define G1_STAGE_H 18432
#define G1_DSMEM (3 * G1_STAGE_H * 2)   // 110592 B

__global__ __launch_bounds__(256, 2) void gemm1(void) {
    extern __shared__ __align__(16) __half sm[];
    const uint32_t smb = smaddr(sm);

    const int h = blockIdx.y;
    int u = blockIdx.x, br = 0;
    while (u >= 16 - br) { u -= 16 - br; br++; }
    const int bc = br + u;
    const int row0 = br * 128, col0 = bc * 128;

    const __half* __restrict__ Qh = g_QRh + (size_t)h * TT * NN;

    const int tid = threadIdx.x;
    const int lane = tid & 31, wid = tid >> 5;
    const int wm = (wid >> 2) * 64, wn = (wid & 3) * 32;
    const int mi = lane >> 3, r8 = lane & 7;
    const int q = lane & 3, l4 = lane >> 2;

    auto load = [&](int stg, int k0) {
        const uint32_t sb = smb + (uint32_t)stg * G1_STAGE_H * 2;
#pragma unroll
        for (int it = 0; it < 8; it++) {
            int c = it * 256 + tid;
            int t = c >> 10;              // 0:A(rows) 1:B(cols)
            int c2 = c & 1023;
            int rr = c2 >> 3, kg = c2 & 7;
            const __half* src =
                (t == 0 ? Qh + (size_t)(row0 + rr) * NN
                        : Qh + (size_t)(col0 + rr) * NN) + k0 + kg * 8;
            cpa16(sb + (uint32_t)(t * 9216 + rr * AP2 + kg * 8) * 2, src);
        }
        cp_commit();
    };

    float acc[4][4][4];
#pragma unroll
    for (int a = 0; a < 4; a++)
#pragma unroll
        for (int b = 0; b < 4; b++)
#pragma unroll
            for (int cc = 0; cc < 4; cc++) acc[a][b][cc] = 0.0f;

    const int NS = NN / 64;
    load(0, 0);
    load(1, 64);

    for (int s = 0; s < NS; s++) {
        if (s + 1 < NS) cp_wait<1>(); else cp_wait<0>();
        __syncthreads();
        if (s + 2 < NS) load((s + 2) % 3, (s + 2) * 64);   // early issue (buffer free per sync)
        const __half* st = sm + (size_t)(s % 3) * G1_STAGE_H;
        const __half* sA = st;
        const __half* sB = st + 9216;
#pragma unroll
        for (int kk = 0; kk < 64; kk += 16) {
            uint32_t fbh[4][2];
#pragma unroll
            for (int p = 0; p < 2; p++) {
                uint32_t r[4];
                ldsm4(r, smaddr(sB + (size_t)(wn + p * 16 + (mi >> 1) * 8 + r8) * AP2 + kk + (mi & 1) * 8));
                fbh[p * 2][0] = r[0]; fbh[p * 2][1] = r[1];
                fbh[p * 2 + 1][0] = r[2]; fbh[p * 2 + 1][1] = r[3];
            }
            uint32_t fa[2][4];
            ldsm4(fa[0], smaddr(sA + (size_t)(wm + (mi & 1) * 8 + r8) * AP2 + kk + (mi >> 1) * 8));
#pragma unroll
            for (int mt = 0; mt < 4; mt++) {
                if (mt < 3)
                    ldsm4(fa[(mt + 1) & 1],
                          smaddr(sA + (size_t)(wm + (mt + 1) * 16 + (mi & 1) * 8 + r8) * AP2 + kk + (mi >> 1) * 8));
#pragma unroll
                for (int nt = 0; nt < 4; nt++)
                    mmaf16(acc[mt][nt], fa[mt & 1], fbh[nt]);
            }
        }
    }

    __half* Sh = g_Sh + (size_t)h * TT * TT;
    const bool mirror = (br != bc);

    // direct writes (scale folded into QR)
#pragma unroll
    for (int mt = 0; mt < 4; mt++)
#pragma unroll
        for (int nt = 0; nt < 4; nt++) {
            int c = col0 + wn + nt * 8 + q * 2;
#pragma unroll
            for (int hh = 0; hh < 2; hh++) {
                int r = row0 + wm + mt * 16 + l4 + hh * 8;
                __half h0 = __float2half_rn(acc[mt][nt][hh * 2 + 0]);
                __half h1 = __float2half_rn(acc[mt][nt][hh * 2 + 1]);
                *(__half2*)&Sh[(size_t)r * TT + c] = __halves2half2(h0, h1);
            }
        }

    // mirror writes via smem transpose
    if (mirror) {
        __syncthreads();
        __half* tsh = sm;
#pragma unroll
        for (int mt = 0; mt < 4; mt++)
#pragma unroll
            for (int nt = 0; nt < 4; nt++)
#pragma unroll
                for (int hh = 0; hh < 2; hh++) {
                    int rl = wm + mt * 16 + l4 + hh * 8;
                    int cl = wn + nt * 8 + q * 2;
                    tsh[(size_t)cl * TRPITCH + rl] = __float2half_rn(acc[mt][nt][hh * 2 + 0]);
                    tsh[(size_t)(cl + 1) * TRPITCH + rl] = __float2half_rn(acc[mt][nt][hh * 2 + 1]);
                }
        __syncthreads();
        int cr = tid >> 1, cb2 = (tid & 1) * 64;
        size_t base = (size_t)(col0 + cr) * TT + row0 + cb2;
#pragma unroll
        for (int j = 0; j < 8; j++)
            *(uint4*)&Sh[base + j * 8] = *(uint4*)&tsh[(size_t)cr * TRPITCH + cb2 + j * 8];
    }
}

// ---------------------------------------------------------------------------
// Kernel 3: O = S V  (single term; K-chunk 64; 3 stages; 2 CTAs/SM;
// A-fragment double-buffered; next-stage load issued right after the barrier)
// stage: A[128][AP2] (9216 h) + B[64][BPITCH] (8704 h) = 17920 h
// ---------------------------------------------------------------------------
#define G2_STAGE_H 17920
#define G2_DSMEM (3 * G2_STAGE_H * 2)   // 107520 B

__global__ __launch_bounds__(256, 2) void gemm2(float* __restrict__ O) {
    extern __shared__ __align__(16) __half sm[];
    const uint32_t smb = smaddr(sm);

    const int h = blockIdx.z;
    const int col0 = blockIdx.x * 128, row0 = blockIdx.y * 128;

    const __half* __restrict__ Sh = g_Sh + (size_t)h * TT * TT;
    const __half* __restrict__ Vh = g_Vh + (size_t)h * TT * NN;
    float* __restrict__ Oh = O + (size_t)h * TT * NN;

    const int tid = threadIdx.x;
    const int lane = tid & 31, wid = tid >> 5;
    const int wm = (wid >> 2) * 64, wn = (wid & 3) * 32;
    const int mi = lane >> 3, r8 = lane & 7;
    const int q = lane & 3, l4 = lane >> 2;

    auto load = [&](int stg, int k0) {
        const uint32_t sb = smb + (uint32_t)stg * G2_STAGE_H * 2;
#pragma unroll
        for (int it = 0; it < 8; it++) {
            int c = it * 256 + tid;
            int t = c >> 10;              // 0:A 1:B
            int c2 = c & 1023;
            if (t == 0) {
                int rr = c2 >> 3, kg = c2 & 7;
                cpa16(sb + (uint32_t)(rr * AP2 + kg * 8) * 2,
                      Sh + (size_t)(row0 + rr) * TT + k0 + kg * 8);
            } else {
                int rr = c2 >> 4, cg = c2 & 15;
                cpa16(sb + (uint32_t)(9216 + rr * BPITCH + cg * 8) * 2,
                      Vh + (size_t)(k0 + rr) * NN + col0 + cg * 8);
            }
        }
        cp_commit();
    };

    float acc[4][4][4];
#pragma unroll
    for (int a = 0; a < 4; a++)
#pragma unroll
        for (int b = 0; b < 4; b++)
#pragma unroll
            for (int cc = 0; cc < 4; cc++) acc[a][b][cc] = 0.0f;

    const int NS = TT / 64;
    load(0, 0);
    load(1, 64);

    for (int s = 0; s < NS; s++) {
        if (s + 1 < NS) cp_wait<1>(); else cp_wait<0>();
        __syncthreads();
        if (s + 2 < NS) load((s + 2) % 3, (s + 2) * 64);   // early issue
        const __half* st = sm + (size_t)(s % 3) * G2_STAGE_H;
        const __half* sA = st;
        const __half* sB = st + 9216;
#pragma unroll
        for (int kk = 0; kk < 64; kk += 16) {
            uint32_t fbh[4][2];
#pragma unroll
            for (int p = 0; p < 2; p++) {
                uint32_t r[4];
                ldsm4t(r, smaddr(sB + (size_t)(kk + (mi & 1) * 8 + r8) * BPITCH + wn + p * 16 + (mi >> 1) * 8));
                fbh[p * 2][0] = r[0]; fbh[p * 2][1] = r[1];
                fbh[p * 2 + 1][0] = r[2]; fbh[p * 2 + 1][1] = r[3];
            }
            uint32_t fa[2][4];
            ldsm4(fa[0], smaddr(sA + (size_t)(wm + (mi & 1) * 8 + r8) * AP2 + kk + (mi >> 1) * 8));
#pragma unroll
            for (int mt = 0; mt < 4; mt++) {
                if (mt < 3)
                    ldsm4(fa[(mt + 1) & 1],
                          smaddr(sA + (size_t)(wm + (mt + 1) * 16 + (mi & 1) * 8 + r8) * AP2 + kk + (mi >> 1) * 8));
#pragma unroll
                for (int nt = 0; nt < 4; nt++)
                    mmaf16(acc[mt][nt], fa[mt & 1], fbh[nt]);
            }
        }
    }

#pragma unroll
    for (int mt = 0; mt < 4; mt++)
#pragma unroll
        for (int nt = 0; nt < 4; nt++) {
            int c = col0 + wn + nt * 8 + q * 2;
#pragma unroll
            for (int hh = 0; hh < 2; hh++) {
                int r = row0 + wm + mt * 16 + l4 + hh * 8;
                *(float2*)&Oh[(size_t)r * NN + c] =
                    make_float2(acc[mt][nt][hh * 2 + 0], acc[mt][nt][hh * 2 + 1]);
            }
        }
}

// ---------------------------------------------------------------------------
// Launch
// ---------------------------------------------------------------------------
extern "C" void kernel_launch(void* const* d_in, const int* in_sizes, int n_in,
                              void* d_out, int out_size) {
    const float* Q = (const float*)d_in[0];
    const float* V = (const float*)d_in[2];
    float* O = (float*)d_out;

    cudaFuncSetAttribute(gemm1, cudaFuncAttributeMaxDynamicSharedMemorySize, G1_DSMEM);
    cudaFuncSetAttribute(gemm2, cudaFuncAttributeMaxDynamicSharedMemorySize, G2_DSMEM);

    {   // merged prep
        prep<<<2 * PREP_BLOCKS, 256>>>(Q, V);
    }
    {   // S (136 upper-tri tiles per head)
        dim3 grid(136, NHT);
        gemm1<<<grid, 256, G1_DSMEM>>>();
    }
    {   // O = S V
        dim3 grid(NN / 128, TT / 128, NHT);
        gemm2<<<grid, 256, G2_DSMEM>>>(O);
    }
}

// round 16
// speedup vs baseline: 1.0697x; 1.0697x over previous
#include <cuda_runtime.h>
#include <cuda_fp16.h>
#include <cstdint>

#define TT 2048
#define NN 4096
#define NHT 8
#define AP2 72       // pitch for 64-wide K tiles (144B rows, conflict-free LDSM)
#define BPITCH 136   // pitch for 128-wide tiles (272B rows, conflict-free LDSM.T)
#define TRPITCH 136

// fp16 scratch (allocation-free device globals)
__device__ __align__(128) __half g_QRh[(size_t)NHT * TT * NN];
__device__ __align__(128) __half g_Vh[(size_t)NHT * TT * NN];
__device__ __align__(128) __half g_Sh[(size_t)NHT * TT * TT];

__device__ __forceinline__ uint32_t smaddr(const void* p) {
    return (uint32_t)__cvta_generic_to_shared(p);
}
__device__ __forceinline__ void ldsm4(uint32_t* r, uint32_t a) {
    asm volatile("ldmatrix.sync.aligned.m8n8.x4.shared.b16 {%0,%1,%2,%3},[%4];"
                 : "=r"(r[0]), "=r"(r[1]), "=r"(r[2]), "=r"(r[3]) : "r"(a));
}
__device__ __forceinline__ void ldsm4t(uint32_t* r, uint32_t a) {
    asm volatile("ldmatrix.sync.aligned.m8n8.x4.trans.shared.b16 {%0,%1,%2,%3},[%4];"
                 : "=r"(r[0]), "=r"(r[1]), "=r"(r[2]), "=r"(r[3]) : "r"(a));
}
__device__ __forceinline__ void mmaf16(float* d, const uint32_t* a, const uint32_t* b) {
    asm volatile("mma.sync.aligned.m16n8k16.row.col.f32.f16.f16.f32 "
                 "{%0,%1,%2,%3},{%4,%5,%6,%7},{%8,%9},{%0,%1,%2,%3};"
                 : "+f"(d[0]), "+f"(d[1]), "+f"(d[2]), "+f"(d[3])
                 : "r"(a[0]), "r"(a[1]), "r"(a[2]), "r"(a[3]), "r"(b[0]), "r"(b[1]));
}
__device__ __forceinline__ void cpa16(uint32_t dst, const void* src) {
    asm volatile("cp.async.cg.shared.global [%0],[%1],16;" :: "r"(dst), "l"(src));
}
__device__ __forceinline__ void cp_commit() { asm volatile("cp.async.commit_group;" ::: "memory"); }
template <int N> __device__ __forceinline__ void cp_wait() {
    asm volatile("cp.async.wait_group %0;" :: "n"(N) : "memory");
}

// ---------------------------------------------------------------------------
// Kernel 1 (merged prep): blocks [0, PB) do RoPE->fp16 (pre-scaled 1/8);
// blocks [PB, 2*PB) do V->fp16.
// ---------------------------------------------------------------------------
#define PREP_BLOCKS 32768   // NHT*TT*NN/8/256

__global__ void prep(const float* __restrict__ Q, const float* __restrict__ V) {
    if (blockIdx.x < PREP_BLOCKS) {
        size_t p0 = ((size_t)blockIdx.x * blockDim.x + threadIdx.x) * 4;  // first pair
        int n2 = (int)(p0 % (NN / 2));
        size_t row = p0 / (NN / 2);
        int t = (int)(row % TT);
        const float inv2pi = 0.15915494309189535f;
        float4 vin0 = *(const float4*)((const float*)Q + p0 * 2);
        float4 vin1 = *(const float4*)((const float*)Q + p0 * 2 + 4);
        float vx[4] = {vin0.x, vin0.z, vin1.x, vin1.z};
        float vy[4] = {vin0.y, vin0.w, vin1.y, vin1.w};
        __half2 out[4];
#pragma unroll
        for (int j = 0; j < 4; j++) {
            float freq = exp2f(-(float)((n2 + j) * 2) * (1.0f / 256.0f)) * inv2pi;
            float ph = (float)t * freq;
            float fr = ph - floorf(ph);
            float s, c;
            sincospif(2.0f * fr, &s, &c);
            float ox = (vx[j] * c - vy[j] * s) * 0.125f;
            float oy = (vy[j] * c + vx[j] * s) * 0.125f;
            out[j] = __halves2half2(__float2half_rn(ox), __float2half_rn(oy));
        }
        *(uint4*)(g_QRh + p0 * 2) = *(uint4*)out;
    } else {
        size_t i = ((size_t)(blockIdx.x - PREP_BLOCKS) * blockDim.x + threadIdx.x) * 8;
        float4 v0 = *(const float4*)(V + i);
        float4 v1 = *(const float4*)(V + i + 4);
        __half2 o[4];
        o[0] = __halves2half2(__float2half_rn(v0.x), __float2half_rn(v0.y));
        o[1] = __halves2half2(__float2half_rn(v0.z), __float2half_rn(v0.w));
        o[2] = __halves2half2(__float2half_rn(v1.x), __float2half_rn(v1.y));
        o[3] = __halves2half2(__float2half_rn(v1.z), __float2half_rn(v1.w));
        *(uint4*)(g_Vh + i) = *(uint4*)o;
    }
}

// ---------------------------------------------------------------------------
// Kernel 2: S = QRs QRs^T  (single term; upper-tri blocks; K-chunk 64,
// 3 stages, 2 CTAs/SM; A-fragment double-buffered across mt; loads issued
// after compute — measured-best placement)
// stage: A[128][AP2] + B[128][AP2] = 18432 halves
// ---------------------------------------------------------------------------
#define G1_STAGE_H 18432
#define G1_DSMEM (3 * G1_STAGE_H * 2)   // 110592 B

__global__ __launch_bounds__(256, 2) void gemm1(void) {
    extern __shared__ __align__(16) __half sm[];
    const uint32_t smb = smaddr(sm);

    const int h = blockIdx.y;
    int u = blockIdx.x, br = 0;
    while (u >= 16 - br) { u -= 16 - br; br++; }
    const int bc = br + u;
    const int row0 = br * 128, col0 = bc * 128;

    const __half* __restrict__ Qh = g_QRh + (size_t)h * TT * NN;

    const int tid = threadIdx.x;
    const int lane = tid & 31, wid = tid >> 5;
    const int wm = (wid >> 2) * 64, wn = (wid & 3) * 32;
    const int mi = lane >> 3, r8 = lane & 7;
    const int q = lane & 3, l4 = lane >> 2;

    auto load = [&](int stg, int k0) {
        const uint32_t sb = smb + (uint32_t)stg * G1_STAGE_H * 2;
#pragma unroll
        for (int it = 0; it < 8; it++) {
            int c = it * 256 + tid;
            int t = c >> 10;              // 0:A(rows) 1:B(cols)
            int c2 = c & 1023;
            int rr = c2 >> 3, kg = c2 & 7;
            const __half* src =
                (t == 0 ? Qh + (size_t)(row0 + rr) * NN
                        : Qh + (size_t)(col0 + rr) * NN) + k0 + kg * 8;
            cpa16(sb + (uint32_t)(t * 9216 + rr * AP2 + kg * 8) * 2, src);
        }
        cp_commit();
    };

    float acc[4][4][4];
#pragma unroll
    for (int a = 0; a < 4; a++)
#pragma unroll
        for (int b = 0; b < 4; b++)
#pragma unroll
            for (int cc = 0; cc < 4; cc++) acc[a][b][cc] = 0.0f;

    const int NS = NN / 64;
    load(0, 0);
    load(1, 64);

    for (int s = 0; s < NS; s++) {
        if (s + 1 < NS) cp_wait<1>(); else cp_wait<0>();
        __syncthreads();
        const __half* st = sm + (size_t)(s % 3) * G1_STAGE_H;
        const __half* sA = st;
        const __half* sB = st + 9216;
#pragma unroll
        for (int kk = 0; kk < 64; kk += 16) {
            uint32_t fbh[4][2];
#pragma unroll
            for (int p = 0; p < 2; p++) {
                uint32_t r[4];
                ldsm4(r, smaddr(sB + (size_t)(wn + p * 16 + (mi >> 1) * 8 + r8) * AP2 + kk + (mi & 1) * 8));
                fbh[p * 2][0] = r[0]; fbh[p * 2][1] = r[1];
                fbh[p * 2 + 1][0] = r[2]; fbh[p * 2 + 1][1] = r[3];
            }
            uint32_t fa[2][4];
            ldsm4(fa[0], smaddr(sA + (size_t)(wm + (mi & 1) * 8 + r8) * AP2 + kk + (mi >> 1) * 8));
#pragma unroll
            for (int mt = 0; mt < 4; mt++) {
                if (mt < 3)
                    ldsm4(fa[(mt + 1) & 1],
                          smaddr(sA + (size_t)(wm + (mt + 1) * 16 + (mi & 1) * 8 + r8) * AP2 + kk + (mi >> 1) * 8));
#pragma unroll
                for (int nt = 0; nt < 4; nt++)
                    mmaf16(acc[mt][nt], fa[mt & 1], fbh[nt]);
            }
        }
        if (s + 2 < NS) load((s + 2) % 3, (s + 2) * 64);
    }

    __half* Sh = g_Sh + (size_t)h * TT * TT;
    const bool mirror = (br != bc);

    // direct writes (scale folded into QR)
#pragma unroll
    for (int mt = 0; mt < 4; mt++)
#pragma unroll
        for (int nt = 0; nt < 4; nt++) {
            int c = col0 + wn + nt * 8 + q * 2;
#pragma unroll
            for (int hh = 0; hh < 2; hh++) {
                int r = row0 + wm + mt * 16 + l4 + hh * 8;
                __half h0 = __float2half_rn(acc[mt][nt][hh * 2 + 0]);
                __half h1 = __float2half_rn(acc[mt][nt][hh * 2 + 1]);
                *(__half2*)&Sh[(size_t)r * TT + c] = __halves2half2(h0, h1);
            }
        }

    if (mirror) {
        __syncthreads();
        __half* tsh = sm;
#pragma unroll
        for (int mt = 0; mt < 4; mt++)
#pragma unroll
            for (int nt = 0; nt < 4; nt++)
#pragma unroll
                for (int hh = 0; hh < 2; hh++) {
                    int rl = wm + mt * 16 + l4 + hh * 8;
                    int cl = wn + nt * 8 + q * 2;
                    tsh[(size_t)cl * TRPITCH + rl] = __float2half_rn(acc[mt][nt][hh * 2 + 0]);
                    tsh[(size_t)(cl + 1) * TRPITCH + rl] = __float2half_rn(acc[mt][nt][hh * 2 + 1]);
                }
        __syncthreads();
        int cr = tid >> 1, cb2 = (tid & 1) * 64;
        size_t base = (size_t)(col0 + cr) * TT + row0 + cb2;
#pragma unroll
        for (int j = 0; j < 8; j++)
            *(uint4*)&Sh[base + j * 8] = *(uint4*)&tsh[(size_t)cr * TRPITCH + cb2 + j * 8];
    }
}

// ---------------------------------------------------------------------------
// Kernel 3: O = S V  (single term; K-chunk 64; 3 stages; 2 CTAs/SM;
// A-fragment double-buffered across mt; loads issued after compute)
// stage: A[128][AP2] (9216 h) + B[64][BPITCH] (8704 h) = 17920 h
// ---------------------------------------------------------------------------
#define G2_STAGE_H 17920
#define G2_DSMEM (3 * G2_STAGE_H * 2)   // 107520 B

__global__ __launch_bounds__(256, 2) void gemm2(float* __restrict__ O) {
    extern __shared__ __align__(16) __half sm[];
    const uint32_t smb = smaddr(sm);

    const int h = blockIdx.z;
    const int col0 = blockIdx.x * 128, row0 = blockIdx.y * 128;

    const __half* __restrict__ Sh = g_Sh + (size_t)h * TT * TT;
    const __half* __restrict__ Vh = g_Vh + (size_t)h * TT * NN;
    float* __restrict__ Oh = O + (size_t)h * TT * NN;

    const int tid = threadIdx.x;
    const int lane = tid & 31, wid = tid >> 5;
    const int wm = (wid >> 2) * 64, wn = (wid & 3) * 32;
    const int mi = lane >> 3, r8 = lane & 7;
    const int q = lane & 3, l4 = lane >> 2;

    auto load = [&](int stg, int k0) {
        const uint32_t sb = smb + (uint32_t)stg * G2_STAGE_H * 2;
#pragma unroll
        for (int it = 0; it < 8; it++) {
            int c = it * 256 + tid;
            int t = c >> 10;              // 0:A 1:B
            int c2 = c & 1023;
            if (t == 0) {
                int rr = c2 >> 3, kg = c2 & 7;
                cpa16(sb + (uint32_t)(rr * AP2 + kg * 8) * 2,
                      Sh + (size_t)(row0 + rr) * TT + k0 + kg * 8);
            } else {
                int rr = c2 >> 4, cg = c2 & 15;
                cpa16(sb + (uint32_t)(9216 + rr * BPITCH + cg * 8) * 2,
                      Vh + (size_t)(k0 + rr) * NN + col0 + cg * 8);
            }
        }
        cp_commit();
    };

    float acc[4][4][4];
#pragma unroll
    for (int a = 0; a < 4; a++)
#pragma unroll
        for (int b = 0; b < 4; b++)
#pragma unroll
            for (int cc = 0; cc < 4; cc++) acc[a][b][cc] = 0.0f;

    const int NS = TT / 64;
    load(0, 0);
    load(1, 64);

    for (int s = 0; s < NS; s++) {
        if (s + 1 < NS) cp_wait<1>(); else cp_wait<0>();
        __syncthreads();
        const __half* st = sm + (size_t)(s % 3) * G2_STAGE_H;
        const __half* sA = st;
        const __half* sB = st + 9216;
#pragma unroll
        for (int kk = 0; kk < 64; kk += 16) {
            uint32_t fbh[4][2];
#pragma unroll
            for (int p = 0; p < 2; p++) {
                uint32_t r[4];
                ldsm4t(r, smaddr(sB + (size_t)(kk + (mi & 1) * 8 + r8) * BPITCH + wn + p * 16 + (mi >> 1) * 8));
                fbh[p * 2][0] = r[0]; fbh[p * 2][1] = r[1];
                fbh[p * 2 + 1][0] = r[2]; fbh[p * 2 + 1][1] = r[3];
            }
            uint32_t fa[2][4];
            ldsm4(fa[0], smaddr(sA + (size_t)(wm + (mi & 1) * 8 + r8) * AP2 + kk + (mi >> 1) * 8));
#pragma unroll
            for (int mt = 0; mt < 4; mt++) {
                if (mt < 3)
                    ldsm4(fa[(mt + 1) & 1],
                          smaddr(sA + (size_t)(wm + (mt + 1) * 16 + (mi & 1) * 8 + r8) * AP2 + kk + (mi >> 1) * 8));
#pragma unroll
                for (int nt = 0; nt < 4; nt++)
                    mmaf16(acc[mt][nt], fa[mt & 1], fbh[nt]);
            }
        }
        if (s + 2 < NS) load((s + 2) % 3, (s + 2) * 64);
    }

#pragma unroll
    for (int mt = 0; mt < 4; mt++)
#pragma unroll
        for (int nt = 0; nt < 4; nt++) {
            int c = col0 + wn + nt * 8 + q * 2;
#pragma unroll
            for (int hh = 0; hh < 2; hh++) {
                int r = row0 + wm + mt * 16 + l4 + hh * 8;
                *(float2*)&Oh[(size_t)r * NN + c] =
                    make_float2(acc[mt][nt][hh * 2 + 0], acc[mt][nt][hh * 2 + 1]);
            }
        }
}

// ---------------------------------------------------------------------------
// Launch
// ---------------------------------------------------------------------------
extern "C" void kernel_launch(void* const* d_in, const int* in_sizes, int n_in,
                              void* d_out, int out_size) {
    const float* Q = (const float*)d_in[0];
    const float* V = (const float*)d_in[2];
    float* O = (float*)d_out;

    cudaFuncSetAttribute(gemm1, cudaFuncAttributeMaxDynamicSharedMemorySize, G1_DSMEM);
    cudaFuncSetAttribute(gemm2, cudaFuncAttributeMaxDynamicSharedMemorySize, G2_DSMEM);

    {   // merged prep: RoPE->fp16 + V->fp16
        prep<<<2 * PREP_BLOCKS, 256>>>(Q, V);
    }
    {   // S (136 upper-tri tiles per head)
        dim3 grid(136, NHT);
        gemm1<<<grid, 256, G1_DSMEM>>>();
    }
    {   // O = S V
        dim3 grid(NN / 128, TT / 128, NHT);
        gemm2<<<grid, 256, G2_DSMEM>>>(O);
    }
}